// round 13
// baseline (speedup 1.0000x reference)
#include <cuda_runtime.h>
#include <cuda_bf16.h>
#include <math.h>

// SimDiff: right[f,i] = cos(x[f,i], x[f+iv, i+1])      (i < tpf-1)
//          down [f,i] = cos(x[f,i], x[f+iv, i+width])  (i < tpf-width)
// else -1. Output: [right | down], each frames*tpf f32.
//
// R12 falsified the LTS-cap model: merging cut L2 traffic 13% and duration
// didn't move. The invariant binder is L1tex data return: 488MB (3 LDG
// streams x every token) at ~44 B/cyc/SM in every fast round, independent of
// where the data comes from. Only lever: fewer LDG bytes per output.
//
// TWO-STEP WARPS: each warp computes 2 consecutive diagonal-chain steps.
// Streams: a0, a1 (= right-target of step0 AND anchor of step1), a2
// (= right-target of step1), c0, c1 (down-targets) -> 5 streams / 2 tokens
// = 2.5 per token (0.833x of R2's 3.0). Norm chain: |a1|^2 serves as step-0
// right-denominator and step-1 anchor norm. 5 in-loop float4 buffers + 9
// accumulators, no smem, no barriers — R2's proven stream shape, less volume.

#define EPSN 1e-8f

template <int NPL>  // D = NPL * 128 floats
__global__ void __launch_bounds__(256, 4) simdiff_2step_kernel(
    const float* __restrict__ x,
    const int* __restrict__ p_frames,
    const int* __restrict__ p_height,
    const int* __restrict__ p_width,
    const int* __restrict__ p_interval,
    float* __restrict__ out,
    int total)
{
    const int width  = *p_width;
    const int height = *p_height;
    const int frames = *p_frames;
    const int iv     = *p_interval;
    const int tpf    = width * height;
    const int D      = NPL * 128;

    // Diagonal chains: step (f += iv, i += 1). Starts: f0 < iv (any i0),
    // or i0 == 0 (f0 in [iv, frames)). Every token on exactly one chain.
    const int nch_a = iv * tpf;
    const int nch_b = frames > iv ? frames - iv : 0;
    const int nch   = nch_a + nch_b;
    const int maxL  = min((frames + iv - 1) / iv, tpf);

    // CTA tile: 2 chains x 4 warp-slots x 2 steps each = 8 steps per chain.
    const int ncb = (nch + 1) >> 1;
    const int nsb = (maxL + 7) >> 3;
    const long ntile = (long)ncb * nsb;

    const int wib  = threadIdx.x >> 5;      // 0..7
    const int lane = threadIdx.x & 31;
    const int jj   = wib & 1;               // chain in tile
    const int kk   = wib >> 1;              // step-pair slot (0..3)

    float* __restrict__ outR = out;
    float* __restrict__ outD = out + total;
    const int dtok = iv * tpf + 1;          // chain step token offset
    const int ctok = iv * tpf + width;      // down-target token offset

    for (long p = blockIdx.x; p < ntile; p += gridDim.x) {
        const int cb = (int)(p % ncb);
        const int sb = (int)(p / ncb);

        const int ci = cb * 2 + jj;
        if (ci >= nch) continue;

        int f0, i0;
        if (ci < nch_a) { f0 = ci % iv; i0 = ci / iv; }
        else            { f0 = iv + (ci - nch_a); i0 = 0; }
        if (f0 >= frames || i0 >= tpf) continue;

        const int Lc = min((frames - f0 + iv - 1) / iv, tpf - i0);
        const int s0 = sb * 8 + kk * 2;
        if (s0 >= Lc) continue;

        const int fA = f0 + s0 * iv;
        const int iA = i0 + s0;
        const int t0 = fA * tpf + iA;

        // Token 0 validity; token 1 exists iff vr0 (right-target on-chain).
        const bool vf0 = (fA + iv) < frames;
        const bool vr0 = vf0 && (iA + 1 < tpf);
        const bool vd0 = vf0 && (iA < tpf - width);

        const int fA1 = fA + iv, iA1 = iA + 1;
        const int t1  = t0 + dtok;
        const bool vf1 = vr0 && ((fA1 + iv) < frames);
        const bool vr1 = vf1 && (iA1 + 1 < tpf);
        const bool vd1 = vf1 && (iA1 < tpf - width);

        // Clamped stream tokens (all in-bounds; bogus results discarded).
        const int ta1 = vr0 ? t1 : t0;
        const int ta2 = vr1 ? t1 + dtok : ta1;
        const int tc0 = vd0 ? t0 + ctok : t0;
        const int tc1 = vd1 ? t1 + ctok : t0;

        const float4* __restrict__ A0 =
            reinterpret_cast<const float4*>(x + (size_t)t0 * D) + lane;
        const float4* __restrict__ A1 =
            reinterpret_cast<const float4*>(x + (size_t)ta1 * D) + lane;
        const float4* __restrict__ A2 =
            reinterpret_cast<const float4*>(x + (size_t)ta2 * D) + lane;
        const float4* __restrict__ C0 =
            reinterpret_cast<const float4*>(x + (size_t)tc0 * D) + lane;
        const float4* __restrict__ C1 =
            reinterpret_cast<const float4*>(x + (size_t)tc1 * D) + lane;

        float n0 = 0.f, n1 = 0.f, n2 = 0.f;          // |a0|^2 |a1|^2 |a2|^2
        float d10 = 0.f, d11 = 0.f;                  // a0.a1, a1.a2
        float d20 = 0.f, d21 = 0.f;                  // a0.c0, a1.c1
        float m0 = 0.f, m1 = 0.f;                    // |c0|^2, |c1|^2

#pragma unroll
        for (int k = 0; k < NPL; k++) {
            const float4 a0 = A0[32 * k];
            const float4 a1 = A1[32 * k];
            const float4 a2 = A2[32 * k];
            const float4 c0 = C0[32 * k];
            const float4 c1 = C1[32 * k];
            n0  = fmaf(a0.x, a0.x, n0);  n0  = fmaf(a0.y, a0.y, n0);
            n0  = fmaf(a0.z, a0.z, n0);  n0  = fmaf(a0.w, a0.w, n0);
            n1  = fmaf(a1.x, a1.x, n1);  n1  = fmaf(a1.y, a1.y, n1);
            n1  = fmaf(a1.z, a1.z, n1);  n1  = fmaf(a1.w, a1.w, n1);
            n2  = fmaf(a2.x, a2.x, n2);  n2  = fmaf(a2.y, a2.y, n2);
            n2  = fmaf(a2.z, a2.z, n2);  n2  = fmaf(a2.w, a2.w, n2);
            d10 = fmaf(a0.x, a1.x, d10); d10 = fmaf(a0.y, a1.y, d10);
            d10 = fmaf(a0.z, a1.z, d10); d10 = fmaf(a0.w, a1.w, d10);
            d11 = fmaf(a1.x, a2.x, d11); d11 = fmaf(a1.y, a2.y, d11);
            d11 = fmaf(a1.z, a2.z, d11); d11 = fmaf(a1.w, a2.w, d11);
            d20 = fmaf(a0.x, c0.x, d20); d20 = fmaf(a0.y, c0.y, d20);
            d20 = fmaf(a0.z, c0.z, d20); d20 = fmaf(a0.w, c0.w, d20);
            d21 = fmaf(a1.x, c1.x, d21); d21 = fmaf(a1.y, c1.y, d21);
            d21 = fmaf(a1.z, c1.z, d21); d21 = fmaf(a1.w, c1.w, d21);
            m0  = fmaf(c0.x, c0.x, m0);  m0  = fmaf(c0.y, c0.y, m0);
            m0  = fmaf(c0.z, c0.z, m0);  m0  = fmaf(c0.w, c0.w, m0);
            m1  = fmaf(c1.x, c1.x, m1);  m1  = fmaf(c1.y, c1.y, m1);
            m1  = fmaf(c1.z, c1.z, m1);  m1  = fmaf(c1.w, c1.w, m1);
        }

#pragma unroll
        for (int off = 16; off > 0; off >>= 1) {
            n0  += __shfl_xor_sync(0xFFFFFFFFu, n0,  off);
            n1  += __shfl_xor_sync(0xFFFFFFFFu, n1,  off);
            n2  += __shfl_xor_sync(0xFFFFFFFFu, n2,  off);
            d10 += __shfl_xor_sync(0xFFFFFFFFu, d10, off);
            d11 += __shfl_xor_sync(0xFFFFFFFFu, d11, off);
            d20 += __shfl_xor_sync(0xFFFFFFFFu, d20, off);
            d21 += __shfl_xor_sync(0xFFFFFFFFu, d21, off);
            m0  += __shfl_xor_sync(0xFFFFFFFFu, m0,  off);
            m1  += __shfl_xor_sync(0xFFFFFFFFu, m1,  off);
        }

        if (lane == 0) {
            const float nA0 = fmaxf(sqrtf(n0), EPSN);
            outR[t0] = vr0 ? d10 / (nA0 * fmaxf(sqrtf(n1), EPSN)) : -1.0f;
            outD[t0] = vd0 ? d20 / (nA0 * fmaxf(sqrtf(m0), EPSN)) : -1.0f;
            if (vr0) {   // token 1 exists exactly when vr0
                const float nA1 = fmaxf(sqrtf(n1), EPSN);
                outR[t1] = vr1 ? d11 / (nA1 * fmaxf(sqrtf(n2), EPSN)) : -1.0f;
                outD[t1] = vd1 ? d21 / (nA1 * fmaxf(sqrtf(m1), EPSN)) : -1.0f;
            }
        }
    }
}

// Generic fallback for arbitrary D (scalar loads, one warp per token).
__global__ void __launch_bounds__(256) simdiff_generic_kernel(
    const float* __restrict__ x,
    const int* __restrict__ p_frames,
    const int* __restrict__ p_height,
    const int* __restrict__ p_width,
    const int* __restrict__ p_interval,
    float* __restrict__ out,
    int total, int D)
{
    const int gwarp = (blockIdx.x * blockDim.x + threadIdx.x) >> 5;
    const int lane  = threadIdx.x & 31;
    if (gwarp >= total) return;

    const int width    = *p_width;
    const int height   = *p_height;
    const int frames   = *p_frames;
    const int interval = *p_interval;
    const int tpf      = width * height;

    const int f = gwarp / tpf;
    const int i = gwarp - f * tpf;

    float* __restrict__ outR = out;
    float* __restrict__ outD = out + total;

    const bool vf = (f + interval) < frames;
    if (!vf) {
        if (lane == 0) { outR[gwarp] = -1.0f; outD[gwarp] = -1.0f; }
        return;
    }
    const bool vr = (i < tpf - 1);
    const bool vd = (i < tpf - width);

    const size_t bframe = (size_t)(f + interval) * tpf + i;
    const size_t i1 = vr ? (bframe + 1)     : bframe;
    const size_t i2 = vd ? (bframe + width) : bframe;

    const float* a = x + (size_t)gwarp * D;
    const float* b = x + i1 * D;
    const float* c = x + i2 * D;

    float na = 0.0f, d1 = 0.0f, n1 = 0.0f, d2 = 0.0f, n2 = 0.0f;
    for (int k = lane; k < D; k += 32) {
        float av = a[k], bv = b[k], cv = c[k];
        na = fmaf(av, av, na);
        d1 = fmaf(av, bv, d1); n1 = fmaf(bv, bv, n1);
        d2 = fmaf(av, cv, d2); n2 = fmaf(cv, cv, n2);
    }

#pragma unroll
    for (int off = 16; off > 0; off >>= 1) {
        na += __shfl_xor_sync(0xFFFFFFFFu, na, off);
        d1 += __shfl_xor_sync(0xFFFFFFFFu, d1, off);
        n1 += __shfl_xor_sync(0xFFFFFFFFu, n1, off);
        d2 += __shfl_xor_sync(0xFFFFFFFFu, d2, off);
        n2 += __shfl_xor_sync(0xFFFFFFFFu, n2, off);
    }

    if (lane == 0) {
        const float nA = fmaxf(sqrtf(na), EPSN);
        outR[gwarp] = vr ? d1 / (nA * fmaxf(sqrtf(n1), EPSN)) : -1.0f;
        outD[gwarp] = vd ? d2 / (nA * fmaxf(sqrtf(n2), EPSN)) : -1.0f;
    }
}

extern "C" void kernel_launch(void* const* d_in, const int* in_sizes, int n_in,
                              void* d_out, int out_size) {
    const float* x        = (const float*)d_in[0];
    const int* p_frames   = (const int*)d_in[1];
    const int* p_height   = (const int*)d_in[2];
    const int* p_width    = (const int*)d_in[3];
    const int* p_interval = (const int*)d_in[4];
    float* out = (float*)d_out;

    const int total = out_size / 2;            // frames * tpf
    const int D     = in_sizes[0] / total;     // hidden dim

    if (D == 1152 || D == 1024 || D == 1280) {
        // ~total/16 useful tiles (16 tokens per CTA) + chain-edge padding;
        // grid-stride covers any shape, surplus tiles exit immediately.
        const int blocks = total / 16 + 1024;
        if (D == 1152) {
            simdiff_2step_kernel<9><<<blocks, 256>>>(
                x, p_frames, p_height, p_width, p_interval, out, total);
        } else if (D == 1024) {
            simdiff_2step_kernel<8><<<blocks, 256>>>(
                x, p_frames, p_height, p_width, p_interval, out, total);
        } else {
            simdiff_2step_kernel<10><<<blocks, 256>>>(
                x, p_frames, p_height, p_width, p_interval, out, total);
        }
    } else {
        const int blocks = (total + 7) / 8;
        simdiff_generic_kernel<<<blocks, 256>>>(
            x, p_frames, p_height, p_width, p_interval, out, total, D);
    }
}

// round 14
// speedup vs baseline: 1.0617x; 1.0617x over previous
#include <cuda_runtime.h>
#include <cuda_bf16.h>
#include <math.h>

// SimDiff: right[f,i] = cos(x[f,i], x[f+iv, i+1])      (i < tpf-1)
//          down [f,i] = cos(x[f,i], x[f+iv, i+width])  (i < tpf-width)
// else -1. Output: [right | down], each frames*tpf f32.
//
// Winning condition (13 rounds of evidence): reduced LDG byte volume AND
// >=40 warps/SM AND a cheap stream body, simultaneously. TWO-STEP warps give
// 5 streams / 2 tokens = 0.833x volume (a1 shared as step-0 right-target and
// step-1 anchor; |a1|^2 chains as denominator+norm). This round meets the
// register budget with FLOAT2 loads: 10 buffer regs instead of 20, total
// ~42-48 -> __launch_bounds__(256,5) holds 40 warps/SM (R2-class
// concurrency). LDG count doubles but wavefront BYTES (the binder) drop 17%,
// and 18 unrolled chunks give ptxas independent loads to hoist.

#define EPSN 1e-8f

template <int NPL>  // D = NPL * 128 floats; float2 chunks = 2*NPL
__global__ void __launch_bounds__(256, 5) simdiff_2step2_kernel(
    const float* __restrict__ x,
    const int* __restrict__ p_frames,
    const int* __restrict__ p_height,
    const int* __restrict__ p_width,
    const int* __restrict__ p_interval,
    float* __restrict__ out,
    int total)
{
    const int width  = *p_width;
    const int height = *p_height;
    const int frames = *p_frames;
    const int iv     = *p_interval;
    const int tpf    = width * height;
    const int D      = NPL * 128;

    // Diagonal chains: step (f += iv, i += 1). Starts: f0 < iv (any i0),
    // or i0 == 0 (f0 in [iv, frames)). Every token on exactly one chain.
    const int nch_a = iv * tpf;
    const int nch_b = frames > iv ? frames - iv : 0;
    const int nch   = nch_a + nch_b;
    const int maxL  = min((frames + iv - 1) / iv, tpf);

    // CTA tile: 2 chains x 4 warp-slots x 2 steps each = 8 steps per chain.
    const int ncb = (nch + 1) >> 1;
    const int nsb = (maxL + 7) >> 3;
    const long ntile = (long)ncb * nsb;

    const int wib  = threadIdx.x >> 5;      // 0..7
    const int lane = threadIdx.x & 31;
    const int jj   = wib & 1;               // chain in tile
    const int kk   = wib >> 1;              // step-pair slot (0..3)

    float* __restrict__ outR = out;
    float* __restrict__ outD = out + total;
    const int dtok = iv * tpf + 1;          // chain step token offset
    const int ctok = iv * tpf + width;      // down-target token offset

    for (long p = blockIdx.x; p < ntile; p += gridDim.x) {
        const int cb = (int)(p % ncb);
        const int sb = (int)(p / ncb);

        const int ci = cb * 2 + jj;
        if (ci >= nch) continue;

        int f0, i0;
        if (ci < nch_a) { f0 = ci % iv; i0 = ci / iv; }
        else            { f0 = iv + (ci - nch_a); i0 = 0; }
        if (f0 >= frames || i0 >= tpf) continue;

        const int Lc = min((frames - f0 + iv - 1) / iv, tpf - i0);
        const int s0 = sb * 8 + kk * 2;
        if (s0 >= Lc) continue;

        const int fA = f0 + s0 * iv;
        const int iA = i0 + s0;
        const int t0 = fA * tpf + iA;

        // Token 0 validity; token 1 exists iff vr0 (right-target on-chain).
        const bool vf0 = (fA + iv) < frames;
        const bool vr0 = vf0 && (iA + 1 < tpf);
        const bool vd0 = vf0 && (iA < tpf - width);

        const int fA1 = fA + iv, iA1 = iA + 1;
        const int t1  = t0 + dtok;
        const bool vf1 = vr0 && ((fA1 + iv) < frames);
        const bool vr1 = vf1 && (iA1 + 1 < tpf);
        const bool vd1 = vf1 && (iA1 < tpf - width);

        // Clamped stream tokens (all in-bounds; bogus results discarded).
        const int ta1 = vr0 ? t1 : t0;
        const int ta2 = vr1 ? t1 + dtok : ta1;
        const int tc0 = vd0 ? t0 + ctok : t0;
        const int tc1 = vd1 ? t1 + ctok : t0;

        const float2* __restrict__ A0 =
            reinterpret_cast<const float2*>(x + (size_t)t0 * D) + lane;
        const float2* __restrict__ A1 =
            reinterpret_cast<const float2*>(x + (size_t)ta1 * D) + lane;
        const float2* __restrict__ A2 =
            reinterpret_cast<const float2*>(x + (size_t)ta2 * D) + lane;
        const float2* __restrict__ C0 =
            reinterpret_cast<const float2*>(x + (size_t)tc0 * D) + lane;
        const float2* __restrict__ C1 =
            reinterpret_cast<const float2*>(x + (size_t)tc1 * D) + lane;

        float n0 = 0.f, n1 = 0.f, n2 = 0.f;          // |a0|^2 |a1|^2 |a2|^2
        float d10 = 0.f, d11 = 0.f;                  // a0.a1, a1.a2
        float d20 = 0.f, d21 = 0.f;                  // a0.c0, a1.c1
        float m0 = 0.f, m1 = 0.f;                    // |c0|^2, |c1|^2

#pragma unroll
        for (int k = 0; k < 2 * NPL; k++) {
            const float2 a0 = A0[32 * k];
            const float2 a1 = A1[32 * k];
            const float2 a2 = A2[32 * k];
            const float2 c0 = C0[32 * k];
            const float2 c1 = C1[32 * k];
            n0  = fmaf(a0.x, a0.x, n0);  n0  = fmaf(a0.y, a0.y, n0);
            n1  = fmaf(a1.x, a1.x, n1);  n1  = fmaf(a1.y, a1.y, n1);
            n2  = fmaf(a2.x, a2.x, n2);  n2  = fmaf(a2.y, a2.y, n2);
            d10 = fmaf(a0.x, a1.x, d10); d10 = fmaf(a0.y, a1.y, d10);
            d11 = fmaf(a1.x, a2.x, d11); d11 = fmaf(a1.y, a2.y, d11);
            d20 = fmaf(a0.x, c0.x, d20); d20 = fmaf(a0.y, c0.y, d20);
            d21 = fmaf(a1.x, c1.x, d21); d21 = fmaf(a1.y, c1.y, d21);
            m0  = fmaf(c0.x, c0.x, m0);  m0  = fmaf(c0.y, c0.y, m0);
            m1  = fmaf(c1.x, c1.x, m1);  m1  = fmaf(c1.y, c1.y, m1);
        }

#pragma unroll
        for (int off = 16; off > 0; off >>= 1) {
            n0  += __shfl_xor_sync(0xFFFFFFFFu, n0,  off);
            n1  += __shfl_xor_sync(0xFFFFFFFFu, n1,  off);
            n2  += __shfl_xor_sync(0xFFFFFFFFu, n2,  off);
            d10 += __shfl_xor_sync(0xFFFFFFFFu, d10, off);
            d11 += __shfl_xor_sync(0xFFFFFFFFu, d11, off);
            d20 += __shfl_xor_sync(0xFFFFFFFFu, d20, off);
            d21 += __shfl_xor_sync(0xFFFFFFFFu, d21, off);
            m0  += __shfl_xor_sync(0xFFFFFFFFu, m0,  off);
            m1  += __shfl_xor_sync(0xFFFFFFFFu, m1,  off);
        }

        if (lane == 0) {
            const float nA0 = fmaxf(sqrtf(n0), EPSN);
            outR[t0] = vr0 ? d10 / (nA0 * fmaxf(sqrtf(n1), EPSN)) : -1.0f;
            outD[t0] = vd0 ? d20 / (nA0 * fmaxf(sqrtf(m0), EPSN)) : -1.0f;
            if (vr0) {   // token 1 exists exactly when vr0
                const float nA1 = fmaxf(sqrtf(n1), EPSN);
                outR[t1] = vr1 ? d11 / (nA1 * fmaxf(sqrtf(n2), EPSN)) : -1.0f;
                outD[t1] = vd1 ? d21 / (nA1 * fmaxf(sqrtf(m1), EPSN)) : -1.0f;
            }
        }
    }
}

// Generic fallback for arbitrary D (scalar loads, one warp per token).
__global__ void __launch_bounds__(256) simdiff_generic_kernel(
    const float* __restrict__ x,
    const int* __restrict__ p_frames,
    const int* __restrict__ p_height,
    const int* __restrict__ p_width,
    const int* __restrict__ p_interval,
    float* __restrict__ out,
    int total, int D)
{
    const int gwarp = (blockIdx.x * blockDim.x + threadIdx.x) >> 5;
    const int lane  = threadIdx.x & 31;
    if (gwarp >= total) return;

    const int width    = *p_width;
    const int height   = *p_height;
    const int frames   = *p_frames;
    const int interval = *p_interval;
    const int tpf      = width * height;

    const int f = gwarp / tpf;
    const int i = gwarp - f * tpf;

    float* __restrict__ outR = out;
    float* __restrict__ outD = out + total;

    const bool vf = (f + interval) < frames;
    if (!vf) {
        if (lane == 0) { outR[gwarp] = -1.0f; outD[gwarp] = -1.0f; }
        return;
    }
    const bool vr = (i < tpf - 1);
    const bool vd = (i < tpf - width);

    const size_t bframe = (size_t)(f + interval) * tpf + i;
    const size_t i1 = vr ? (bframe + 1)     : bframe;
    const size_t i2 = vd ? (bframe + width) : bframe;

    const float* a = x + (size_t)gwarp * D;
    const float* b = x + i1 * D;
    const float* c = x + i2 * D;

    float na = 0.0f, d1 = 0.0f, n1 = 0.0f, d2 = 0.0f, n2 = 0.0f;
    for (int k = lane; k < D; k += 32) {
        float av = a[k], bv = b[k], cv = c[k];
        na = fmaf(av, av, na);
        d1 = fmaf(av, bv, d1); n1 = fmaf(bv, bv, n1);
        d2 = fmaf(av, cv, d2); n2 = fmaf(cv, cv, n2);
    }

#pragma unroll
    for (int off = 16; off > 0; off >>= 1) {
        na += __shfl_xor_sync(0xFFFFFFFFu, na, off);
        d1 += __shfl_xor_sync(0xFFFFFFFFu, d1, off);
        n1 += __shfl_xor_sync(0xFFFFFFFFu, n1, off);
        d2 += __shfl_xor_sync(0xFFFFFFFFu, d2, off);
        n2 += __shfl_xor_sync(0xFFFFFFFFu, n2, off);
    }

    if (lane == 0) {
        const float nA = fmaxf(sqrtf(na), EPSN);
        outR[gwarp] = vr ? d1 / (nA * fmaxf(sqrtf(n1), EPSN)) : -1.0f;
        outD[gwarp] = vd ? d2 / (nA * fmaxf(sqrtf(n2), EPSN)) : -1.0f;
    }
}

extern "C" void kernel_launch(void* const* d_in, const int* in_sizes, int n_in,
                              void* d_out, int out_size) {
    const float* x        = (const float*)d_in[0];
    const int* p_frames   = (const int*)d_in[1];
    const int* p_height   = (const int*)d_in[2];
    const int* p_width    = (const int*)d_in[3];
    const int* p_interval = (const int*)d_in[4];
    float* out = (float*)d_out;

    const int total = out_size / 2;            // frames * tpf
    const int D     = in_sizes[0] / total;     // hidden dim

    if (D == 1152 || D == 1024 || D == 1280) {
        // ~total/16 useful tiles (16 tokens per CTA) + chain-edge padding;
        // grid-stride covers any shape, surplus tiles exit immediately.
        const int blocks = total / 16 + 1024;
        if (D == 1152) {
            simdiff_2step2_kernel<9><<<blocks, 256>>>(
                x, p_frames, p_height, p_width, p_interval, out, total);
        } else if (D == 1024) {
            simdiff_2step2_kernel<8><<<blocks, 256>>>(
                x, p_frames, p_height, p_width, p_interval, out, total);
        } else {
            simdiff_2step2_kernel<10><<<blocks, 256>>>(
                x, p_frames, p_height, p_width, p_interval, out, total);
        }
    } else {
        const int blocks = (total + 7) / 8;
        simdiff_generic_kernel<<<blocks, 256>>>(
            x, p_frames, p_height, p_width, p_interval, out, total, D);
    }
}